// round 1
// baseline (speedup 1.0000x reference)
#include <cuda_runtime.h>
#include <cuda_bf16.h>
#include <cstdint>
#include <cstddef>

// Problem constants
#define B_ 4
#define N_ 256
#define D_ 256
#define H_ 8
#define DK_ 32
#define DV_ 32
#define R_ 64
#define BN_ (B_*N_)          // 1024 rows
#define EPS_ 1e-6f

// ---------------- device scratch ----------------
__device__ float g_ER[R_ * D_];                  // relationE @ Wr   [64,256]
__device__ float g_EV[R_ * D_];                  // relationE @ Wvv  [64,256]
__device__ float g_Xq[B_ * H_ * N_ * DK_];       // [b,h,i,d]
__device__ float g_Xk[B_ * H_ * N_ * DK_];
__device__ float g_Xv[B_ * H_ * N_ * DV_];
__device__ float g_Pq[B_ * N_ * H_ * R_];        // [b,i,h,r]
__device__ float g_S0[B_ * H_ * N_ * N_];        // qk logits (unscaled)
__device__ float g_Z2[B_ * H_ * N_ * DV_];       // relation value term
__device__ float g_Zc[BN_ * D_];                 // [b,i, h*DV+d]
__device__ float g_T [BN_ * D_];                 // Zc @ Wo (pre-LN)

// ---------------- block reductions ----------------
__device__ __forceinline__ float block_reduce_max(float v, float* red) {
    #pragma unroll
    for (int o = 16; o > 0; o >>= 1) v = fmaxf(v, __shfl_xor_sync(0xffffffffu, v, o));
    if ((threadIdx.x & 31) == 0) red[threadIdx.x >> 5] = v;
    __syncthreads();
    if (threadIdx.x < 32) {
        float r = (threadIdx.x < 8) ? red[threadIdx.x] : -3.4e38f;
        #pragma unroll
        for (int o = 4; o > 0; o >>= 1) r = fmaxf(r, __shfl_xor_sync(0xffffffffu, r, o));
        if (threadIdx.x == 0) red[8] = r;
    }
    __syncthreads();
    float out = red[8];
    __syncthreads();
    return out;
}

__device__ __forceinline__ float block_reduce_sum(float v, float* red) {
    #pragma unroll
    for (int o = 16; o > 0; o >>= 1) v += __shfl_xor_sync(0xffffffffu, v, o);
    if ((threadIdx.x & 31) == 0) red[threadIdx.x >> 5] = v;
    __syncthreads();
    if (threadIdx.x < 32) {
        float r = (threadIdx.x < 8) ? red[threadIdx.x] : 0.0f;
        #pragma unroll
        for (int o = 4; o > 0; o >>= 1) r += __shfl_xor_sync(0xffffffffu, r, o);
        if (threadIdx.x == 0) red[8] = r;
    }
    __syncthreads();
    float out = red[8];
    __syncthreads();
    return out;
}

// ---------------- 1) ER = relationE @ Wr,  EV = relationE @ Wvv ----------------
__global__ void __launch_bounds__(256)
calcE_kernel(const float* __restrict__ relE, const float* __restrict__ Wr,
             const float* __restrict__ Wvv) {
    int r = blockIdx.x;                      // 0..63
    const float* W = (blockIdx.y == 0) ? Wr : Wvv;
    float* O = (blockIdx.y == 0) ? g_ER : g_EV;
    __shared__ float re[D_];
    re[threadIdx.x] = relE[r * D_ + threadIdx.x];
    __syncthreads();
    int e = threadIdx.x;
    float acc = 0.f;
    #pragma unroll 4
    for (int d = 0; d < D_; d++) acc = fmaf(re[d], W[d * D_ + e], acc);
    O[r * D_ + e] = acc;
}

// ---------------- 2) projections: Xq/Xk/Xv = q @ {Wq,Wk,Wv}, head layout -------
__global__ void __launch_bounds__(256)
proj_kernel(const float* __restrict__ X, const float* __restrict__ Wq,
            const float* __restrict__ Wk, const float* __restrict__ Wv) {
    const float* W = (blockIdx.z == 0) ? Wq : (blockIdx.z == 1) ? Wk : Wv;
    float* O = (blockIdx.z == 0) ? g_Xq : (blockIdx.z == 1) ? g_Xk : g_Xv;
    __shared__ float As[16][65];   // [k][m]
    __shared__ float Bs[16][65];   // [k][n]
    int m0 = blockIdx.y * 64, n0 = blockIdx.x * 64;
    int tid = threadIdx.x;
    int tx = tid & 15, ty = tid >> 4;
    float acc[4][4] = {};
    for (int k0 = 0; k0 < D_; k0 += 16) {
        for (int l = tid; l < 64 * 16; l += 256) {
            int m = l >> 4, k = l & 15;
            As[k][m] = X[(m0 + m) * D_ + k0 + k];
        }
        for (int l = tid; l < 64 * 16; l += 256) {
            int k = l >> 6, n = l & 63;
            Bs[k][n] = W[(k0 + k) * D_ + n0 + n];
        }
        __syncthreads();
        #pragma unroll
        for (int k = 0; k < 16; k++) {
            float a[4], b[4];
            #pragma unroll
            for (int u = 0; u < 4; u++) a[u] = As[k][ty * 4 + u];
            #pragma unroll
            for (int w = 0; w < 4; w++) b[w] = Bs[k][tx * 4 + w];
            #pragma unroll
            for (int u = 0; u < 4; u++)
                #pragma unroll
                for (int w = 0; w < 4; w++) acc[u][w] = fmaf(a[u], b[w], acc[u][w]);
        }
        __syncthreads();
    }
    #pragma unroll
    for (int u = 0; u < 4; u++)
        #pragma unroll
        for (int w = 0; w < 4; w++) {
            int m = m0 + ty * 4 + u, e = n0 + tx * 4 + w;
            int b = m >> 8, i = m & 255, h = e >> 5, d = e & 31;
            O[(((b * H_ + h) * N_) + i) * DK_ + d] = acc[u][w];
        }
}

// ---------------- 3) Pq[b,i,h,r] = Xq[b,h,i,:] . ER[r, h*32:...] --------------
__global__ void __launch_bounds__(256)
pq_kernel() {
    int h = blockIdx.x, b = blockIdx.y;
    __shared__ float xq[N_ * 33];   // padded rows
    __shared__ float er[R_ * 32];
    int tid = threadIdx.x;
    const float* Xq = g_Xq + ((size_t)(b * H_ + h) * N_) * DK_;
    for (int l = tid; l < N_ * 32; l += 256) {
        int i = l >> 5, d = l & 31;
        xq[i * 33 + d] = Xq[l];
    }
    for (int l = tid; l < R_ * 32; l += 256) {
        int r = l >> 5, d = l & 31;
        er[l] = g_ER[r * D_ + h * 32 + d];
    }
    __syncthreads();
    int i = tid;
    #pragma unroll 2
    for (int r = 0; r < R_; r++) {
        float acc = 0.f;
        #pragma unroll
        for (int d = 0; d < 32; d++) acc = fmaf(xq[i * 33 + d], er[r * 32 + d], acc);
        g_Pq[(((size_t)(b * N_ + i)) * H_ + h) * R_ + r] = acc;
    }
}

// ---------------- 4) S0[b,h,i,j] = Xq[b,h,i,:] . Xk[b,h,j,:] ------------------
__global__ void __launch_bounds__(256)
s0_kernel() {
    int bh = blockIdx.z;
    const float* Xq = g_Xq + (size_t)bh * N_ * DK_;
    const float* Xk = g_Xk + (size_t)bh * N_ * DK_;
    __shared__ float A[64][33];
    __shared__ float Bs[64][33];
    int i0 = blockIdx.y * 64, j0 = blockIdx.x * 64;
    int tid = threadIdx.x;
    for (int l = tid; l < 64 * 32; l += 256) {
        int rr = l >> 5, d = l & 31;
        A[rr][d]  = Xq[(i0 + rr) * DK_ + d];
        Bs[rr][d] = Xk[(j0 + rr) * DK_ + d];
    }
    __syncthreads();
    int tx = tid & 15, ty = tid >> 4;
    float acc[4][4] = {};
    #pragma unroll
    for (int d = 0; d < 32; d++) {
        float a[4], bb[4];
        #pragma unroll
        for (int u = 0; u < 4; u++) a[u] = A[ty * 4 + u][d];
        #pragma unroll
        for (int w = 0; w < 4; w++) bb[w] = Bs[tx * 4 + w][d];
        #pragma unroll
        for (int u = 0; u < 4; u++)
            #pragma unroll
            for (int w = 0; w < 4; w++) acc[u][w] = fmaf(a[u], bb[w], acc[u][w]);
    }
    float* out = g_S0 + (size_t)bh * N_ * N_;
    #pragma unroll
    for (int u = 0; u < 4; u++)
        #pragma unroll
        for (int w = 0; w < 4; w++)
            out[(i0 + ty * 4 + u) * N_ + j0 + tx * 4 + w] = acc[u][w];
}

// ---------------- 5) fused: bias + softmax + alpha + W + Z2 -------------------
// one block per (b,i). link[b,i,:,:] (256x64) loaded once into padded smem.
#define LPAD 68
#define SMEM_C_FLOATS (N_ * LPAD + H_ * R_ + H_ * N_ + H_ * R_ + 64)

__global__ void __launch_bounds__(256)
fused_attn_kernel(const float* __restrict__ link, const int* __restrict__ mask,
                  float* __restrict__ alpha_out) {
    extern __shared__ float sm[];
    float* L    = sm;                       // 256*68
    float* pq   = L + N_ * LPAD;            // 512
    float* aS   = pq + H_ * R_;             // 2048
    float* wsh  = aS + H_ * N_;             // 512
    float* red  = wsh + H_ * R_;            // 64

    int bi = blockIdx.x;
    int b = bi >> 8, i = bi & 255;
    int tid = threadIdx.x;

    // load link tile (contiguous 64KB) into padded smem
    const float4* src = (const float4*)(link + (size_t)bi * (N_ * R_));
    for (int l = tid; l < N_ * R_ / 4; l += 256) {
        float4 v = src[l];
        int j = l >> 4;
        int r4 = (l & 15) << 2;
        float* dst = L + j * LPAD + r4;
        dst[0] = v.x; dst[1] = v.y; dst[2] = v.z; dst[3] = v.w;
    }
    // load Pq[b,i,:,:] (512 contiguous floats)
    pq[tid]       = g_Pq[(size_t)bi * (H_ * R_) + tid];
    pq[tid + 256] = g_Pq[(size_t)bi * (H_ * R_) + 256 + tid];
    __syncthreads();

    int j = tid;
    int mval = mask[(size_t)bi * N_ + j];

    // bias[h] for all heads, reading L row once (float4, conflict-free)
    float bias[H_] = {};
    const float4* Lj4 = (const float4*)(L + j * LPAD);
    #pragma unroll
    for (int rc = 0; rc < 16; rc++) {
        float4 lv = Lj4[rc];
        #pragma unroll
        for (int h = 0; h < H_; h++) {
            float4 pv = ((const float4*)(pq + h * R_))[rc];
            bias[h] += lv.x * pv.x + lv.y * pv.y + lv.z * pv.z + lv.w * pv.w;
        }
    }

    const float inv = 0.17677669529663687f;   // 1/sqrt(32)
    #pragma unroll 1
    for (int h = 0; h < H_; h++) {
        float s = g_S0[(((size_t)(b * H_ + h) * N_ + i) * N_) + j];
        float logit = (s + bias[h]) * inv;
        if (mval == 0) logit = -1e9f;
        float m = block_reduce_max(logit, red);
        float p = __expf(logit - m);
        float ssum = block_reduce_sum(p, red);
        float a = p / ssum;
        aS[h * N_ + j] = a;
        alpha_out[(((size_t)(b * H_ + h) * N_ + i) * N_) + j] = a;
    }
    __syncthreads();

    // W[h,r] = sum_j alpha[h,j] * L[j,r]
    #pragma unroll
    for (int p2 = tid; p2 < H_ * R_; p2 += 256) {
        int h = p2 >> 6, r = p2 & 63;
        float acc = 0.f;
        const float* ar = aS + h * N_;
        const float* lr = L + r;
        #pragma unroll 8
        for (int jj = 0; jj < N_; jj++) acc = fmaf(ar[jj], lr[jj * LPAD], acc);
        wsh[p2] = acc;
    }
    __syncthreads();

    // Z2[h,d] = sum_r W[h,r] * EV[r, h*32+d]
    {
        int h = tid >> 5, d = tid & 31;
        float acc = 0.f;
        const float* wr = wsh + h * R_;
        const float* ev = g_EV + h * 32 + d;
        #pragma unroll
        for (int r = 0; r < R_; r++) acc = fmaf(wr[r], ev[r * D_], acc);
        g_Z2[(((size_t)(b * H_ + h) * N_ + i) * DV_) + d] = acc;
    }
}

// ---------------- 6) Z = alpha @ Xv + Z2, write head-concat layout ------------
__global__ void __launch_bounds__(256)
z_kernel(const float* __restrict__ alpha) {
    int bh = blockIdx.y;
    int b = bh >> 3, h = bh & 7;
    int i0 = blockIdx.x * 64;
    __shared__ float A[64][65];
    __shared__ float V[64][33];
    const float* al = alpha + (size_t)bh * N_ * N_;
    const float* Xv = g_Xv + (size_t)bh * N_ * DV_;
    int tid = threadIdx.x;
    int ty = tid >> 5, tx = tid & 31;
    float acc[8] = {};
    for (int j0 = 0; j0 < N_; j0 += 64) {
        for (int l = tid; l < 64 * 64; l += 256) {
            int ii = l >> 6, jj = l & 63;
            A[ii][jj] = al[(i0 + ii) * N_ + j0 + jj];
        }
        for (int l = tid; l < 64 * 32; l += 256) {
            int jj = l >> 5, d = l & 31;
            V[jj][d] = Xv[(j0 + jj) * DV_ + d];
        }
        __syncthreads();
        #pragma unroll 8
        for (int jj = 0; jj < 64; jj++) {
            float vv = V[jj][tx];
            #pragma unroll
            for (int u = 0; u < 8; u++) acc[u] = fmaf(A[ty * 8 + u][jj], vv, acc[u]);
        }
        __syncthreads();
    }
    #pragma unroll
    for (int u = 0; u < 8; u++) {
        int i = i0 + ty * 8 + u;
        float z = acc[u] + g_Z2[((size_t)bh * N_ + i) * DV_ + tx];
        g_Zc[((size_t)(b * N_ + i)) * D_ + h * DV_ + tx] = z;
    }
}

// ---------------- 7) T = Zc @ Wo ----------------------------------------------
__global__ void __launch_bounds__(256)
out_gemm_kernel(const float* __restrict__ Wo) {
    __shared__ float As[16][65];
    __shared__ float Bs[16][65];
    int m0 = blockIdx.y * 64, n0 = blockIdx.x * 64;
    int tid = threadIdx.x;
    int tx = tid & 15, ty = tid >> 4;
    float acc[4][4] = {};
    for (int k0 = 0; k0 < D_; k0 += 16) {
        for (int l = tid; l < 64 * 16; l += 256) {
            int m = l >> 4, k = l & 15;
            As[k][m] = g_Zc[(size_t)(m0 + m) * D_ + k0 + k];
        }
        for (int l = tid; l < 64 * 16; l += 256) {
            int k = l >> 6, n = l & 63;
            Bs[k][n] = Wo[(k0 + k) * D_ + n0 + n];
        }
        __syncthreads();
        #pragma unroll
        for (int k = 0; k < 16; k++) {
            float a[4], b[4];
            #pragma unroll
            for (int u = 0; u < 4; u++) a[u] = As[k][ty * 4 + u];
            #pragma unroll
            for (int w = 0; w < 4; w++) b[w] = Bs[k][tx * 4 + w];
            #pragma unroll
            for (int u = 0; u < 4; u++)
                #pragma unroll
                for (int w = 0; w < 4; w++) acc[u][w] = fmaf(a[u], b[w], acc[u][w]);
        }
        __syncthreads();
    }
    #pragma unroll
    for (int u = 0; u < 4; u++)
        #pragma unroll
        for (int w = 0; w < 4; w++)
            g_T[(size_t)(m0 + ty * 4 + u) * D_ + n0 + tx * 4 + w] = acc[u][w];
}

// ---------------- 8) residual + LayerNorm -> out ------------------------------
__global__ void __launch_bounds__(256)
ln_kernel(const float* __restrict__ qin, const float* __restrict__ gamma,
          const float* __restrict__ beta, float* __restrict__ out) {
    __shared__ float red[16];
    int row = blockIdx.x;
    int e = threadIdx.x;
    float t = g_T[(size_t)row * D_ + e] + qin[(size_t)row * D_ + e];
    float mu = block_reduce_sum(t, red) * (1.0f / 256.0f);
    float dv = t - mu;
    float var = block_reduce_sum(dv * dv, red) * (1.0f / 256.0f);
    out[(size_t)row * D_ + e] = dv * rsqrtf(var + EPS_) * gamma[e] + beta[e];
}

// ---------------- launch -------------------------------------------------------
extern "C" void kernel_launch(void* const* d_in, const int* in_sizes, int n_in,
                              void* d_out, int out_size) {
    const float* q    = (const float*)d_in[0];
    // d_in[1]=k, d_in[2]=v : unused by this reference branch
    const int*   mask = (const int*)  d_in[3];
    const float* link = (const float*)d_in[4];
    const float* Wq   = (const float*)d_in[5];
    const float* Wk   = (const float*)d_in[6];
    const float* Wr   = (const float*)d_in[7];
    const float* Wv   = (const float*)d_in[8];
    const float* Wvv  = (const float*)d_in[9];
    const float* relE = (const float*)d_in[10];
    const float* Wo   = (const float*)d_in[11];
    const float* gamma= (const float*)d_in[12];
    const float* beta = (const float*)d_in[13];

    float* out_ptr   = (float*)d_out;                      // [B,N,D]
    float* alpha_ptr = (float*)d_out + (size_t)B_ * N_ * D_; // [B,H,N,N]

    static const size_t smemC = SMEM_C_FLOATS * sizeof(float);
    cudaFuncSetAttribute(fused_attn_kernel,
                         cudaFuncAttributeMaxDynamicSharedMemorySize, (int)smemC);

    calcE_kernel<<<dim3(R_, 2), 256>>>(relE, Wr, Wvv);
    proj_kernel<<<dim3(D_ / 64, BN_ / 64, 3), 256>>>(q, Wq, Wk, Wv);
    pq_kernel<<<dim3(H_, B_), 256>>>();
    s0_kernel<<<dim3(N_ / 64, N_ / 64, B_ * H_), 256>>>();
    fused_attn_kernel<<<BN_, 256, smemC>>>(link, mask, alpha_ptr);
    z_kernel<<<dim3(N_ / 64, B_ * H_), 256>>>(alpha_ptr);
    out_gemm_kernel<<<dim3(D_ / 64, BN_ / 64), 256>>>(Wo);
    ln_kernel<<<BN_, 256>>>(q, gamma, beta, out_ptr);
}

// round 2
// speedup vs baseline: 2.1325x; 2.1325x over previous
#include <cuda_runtime.h>
#include <cuda_bf16.h>
#include <cstdint>
#include <cstddef>

// Problem constants
#define B_ 4
#define N_ 256
#define D_ 256
#define H_ 8
#define DK_ 32
#define DV_ 32
#define R_ 64
#define BN_ (B_*N_)
#define EPS_ 1e-6f

// ---------------- device scratch ----------------
__device__ float g_ER[R_ * D_];                  // relationE @ Wr   [64,256]
__device__ float g_EV[R_ * D_];                  // relationE @ Wvv  [64,256]
__device__ float g_Xq[B_ * H_ * N_ * DK_];       // [b,h,i,d]
__device__ float g_Xk[B_ * H_ * N_ * DK_];
__device__ float g_Xv[B_ * H_ * N_ * DV_];
__device__ float g_Pq[B_ * N_ * H_ * R_];        // [b,i,h*64+r]
__device__ float g_S0[B_ * H_ * N_ * N_];        // qk logits (unscaled)
__device__ float g_Z2[B_ * H_ * N_ * DV_];
__device__ float g_Zc[BN_ * D_];                 // [b,i, h*DV+d]
__device__ float g_T [BN_ * D_];                 // Zc @ Wo (pre-LN)

__device__ __forceinline__ float block_reduce_sum(float v, float* red) {
    #pragma unroll
    for (int o = 16; o > 0; o >>= 1) v += __shfl_xor_sync(0xffffffffu, v, o);
    if ((threadIdx.x & 31) == 0) red[threadIdx.x >> 5] = v;
    __syncthreads();
    if (threadIdx.x < 32) {
        float r = (threadIdx.x < 8) ? red[threadIdx.x] : 0.0f;
        #pragma unroll
        for (int o = 4; o > 0; o >>= 1) r += __shfl_xor_sync(0xffffffffu, r, o);
        if (threadIdx.x == 0) red[8] = r;
    }
    __syncthreads();
    float out = red[8];
    __syncthreads();
    return out;
}

// ---------------- 1) ER = relationE @ Wr,  EV = relationE @ Wvv ----------------
__global__ void __launch_bounds__(256)
calcE_kernel(const float* __restrict__ relE, const float* __restrict__ Wr,
             const float* __restrict__ Wvv) {
    int r = blockIdx.x;
    const float* W = (blockIdx.y == 0) ? Wr : Wvv;
    float* O = (blockIdx.y == 0) ? g_ER : g_EV;
    __shared__ float re[D_];
    re[threadIdx.x] = relE[r * D_ + threadIdx.x];
    __syncthreads();
    int e = threadIdx.x;
    float acc = 0.f;
    #pragma unroll 4
    for (int d = 0; d < D_; d++) acc = fmaf(re[d], W[d * D_ + e], acc);
    O[r * D_ + e] = acc;
}

// ---------------- 2) projections: Xq/Xk/Xv = q @ {Wq,Wk,Wv}, head layout -------
__global__ void __launch_bounds__(256)
proj_kernel(const float* __restrict__ X, const float* __restrict__ Wq,
            const float* __restrict__ Wk, const float* __restrict__ Wv) {
    const float* W = (blockIdx.z == 0) ? Wq : (blockIdx.z == 1) ? Wk : Wv;
    float* O = (blockIdx.z == 0) ? g_Xq : (blockIdx.z == 1) ? g_Xk : g_Xv;
    __shared__ float As[16 * 68];   // [k][m]
    __shared__ float Bs[16 * 68];   // [k][n]
    int m0 = blockIdx.y * 64, n0 = blockIdx.x * 64;
    int tid = threadIdx.x;
    int tx = tid & 15, ty = tid >> 4;
    float acc[4][4] = {};
    const float4* X4 = (const float4*)X;
    const float4* W4 = (const float4*)W;
    for (int k0 = 0; k0 < D_; k0 += 16) {
        {   // A: 64m x 16k = 256 float4 (over k)
            int m = tid >> 2, kq = tid & 3;
            float4 v = X4[(size_t)(m0 + m) * 64 + (k0 >> 2) + kq];
            As[(4*kq+0)*68 + m] = v.x; As[(4*kq+1)*68 + m] = v.y;
            As[(4*kq+2)*68 + m] = v.z; As[(4*kq+3)*68 + m] = v.w;
        }
        {   // B: 16k x 64n = 256 float4 (over n)
            int k = tid >> 4, nq = tid & 15;
            float4 v = W4[(size_t)(k0 + k) * 64 + (n0 >> 2) + nq];
            *(float4*)(Bs + k * 68 + nq * 4) = v;
        }
        __syncthreads();
        #pragma unroll
        for (int k = 0; k < 16; k++) {
            float4 a = *(const float4*)(As + k * 68 + ty * 4);
            float4 b = *(const float4*)(Bs + k * 68 + tx * 4);
            float av[4] = {a.x, a.y, a.z, a.w};
            float bv[4] = {b.x, b.y, b.z, b.w};
            #pragma unroll
            for (int u = 0; u < 4; u++)
                #pragma unroll
                for (int w = 0; w < 4; w++) acc[u][w] = fmaf(av[u], bv[w], acc[u][w]);
        }
        __syncthreads();
    }
    #pragma unroll
    for (int u = 0; u < 4; u++)
        #pragma unroll
        for (int w = 0; w < 4; w++) {
            int m = m0 + ty * 4 + u, e = n0 + tx * 4 + w;
            int b = m >> 8, i = m & 255, h = e >> 5, d = e & 31;
            O[(((b * H_ + h) * N_) + i) * DK_ + d] = acc[u][w];
        }
}

// ---------------- 3) Pq[b,i,h,r] ------------------------------------------------
__global__ void __launch_bounds__(256)
pq_kernel() {
    int h = blockIdx.x, b = blockIdx.y, i0 = blockIdx.z * 64;
    __shared__ float xq[64 * 36];
    __shared__ float er[64 * 32];
    __shared__ float st[64 * 65];
    int tid = threadIdx.x;
    const float4* Xq4 = (const float4*)(g_Xq + ((size_t)(b * H_ + h) * N_ + i0) * DK_);
    #pragma unroll
    for (int p = 0; p < 2; p++) {
        int l = tid + p * 256;
        int ii = l >> 3, dq = l & 7;
        float4 v = Xq4[ii * 8 + dq];
        *(float4*)(xq + ii * 36 + dq * 4) = v;
    }
    #pragma unroll
    for (int p = 0; p < 2; p++) {
        int l = tid + p * 256;
        int r = l >> 3, dq = l & 7;
        float4 v = *(const float4*)(g_ER + (size_t)r * D_ + h * 32 + dq * 4);
        *(float4*)(er + r * 32 + dq * 4) = v;
    }
    __syncthreads();
    int ii = tid & 63, rg = tid >> 6;
    #pragma unroll
    for (int rr = 0; rr < 16; rr++) {
        int r = rg * 16 + rr;
        float acc = 0.f;
        #pragma unroll
        for (int dc = 0; dc < 8; dc++) {
            float4 xv = *(const float4*)(xq + ii * 36 + dc * 4);
            float4 ev = *(const float4*)(er + r * 32 + dc * 4);
            acc = fmaf(xv.x, ev.x, acc); acc = fmaf(xv.y, ev.y, acc);
            acc = fmaf(xv.z, ev.z, acc); acc = fmaf(xv.w, ev.w, acc);
        }
        st[ii * 65 + r] = acc;
    }
    __syncthreads();
    float* dst = g_Pq + ((size_t)(b * N_ + i0)) * 512 + h * 64;
    #pragma unroll
    for (int p = 0; p < 16; p++) {
        int idx = tid + p * 256;
        int iw = idx >> 6, r = idx & 63;
        dst[(size_t)iw * 512 + r] = st[iw * 65 + r];
    }
}

// ---------------- 4) S0 = Xq @ Xk^T, 128x128 tiles ------------------------------
__global__ void __launch_bounds__(256)
s0_kernel() {
    int bh = blockIdx.z;
    const float4* Xq4 = (const float4*)(g_Xq + (size_t)bh * N_ * DK_);
    const float4* Xk4 = (const float4*)(g_Xk + (size_t)bh * N_ * DK_);
    __shared__ float A[32 * 132];   // [k][i]
    __shared__ float Bs[32 * 132];  // [k][j]
    int i0 = blockIdx.y * 128, j0 = blockIdx.x * 128;
    int tid = threadIdx.x;
    #pragma unroll
    for (int p = 0; p < 4; p++) {
        int l = tid + p * 256;
        int row = l >> 3, kq = l & 7;
        float4 va = Xq4[(i0 + row) * 8 + kq];
        A[(4*kq+0)*132 + row] = va.x; A[(4*kq+1)*132 + row] = va.y;
        A[(4*kq+2)*132 + row] = va.z; A[(4*kq+3)*132 + row] = va.w;
        float4 vb = Xk4[(j0 + row) * 8 + kq];
        Bs[(4*kq+0)*132 + row] = vb.x; Bs[(4*kq+1)*132 + row] = vb.y;
        Bs[(4*kq+2)*132 + row] = vb.z; Bs[(4*kq+3)*132 + row] = vb.w;
    }
    __syncthreads();
    int tx = tid & 15, ty = tid >> 4;
    float acc[8][8] = {};
    #pragma unroll
    for (int k = 0; k < 32; k++) {
        float4 a0 = *(const float4*)(A + k * 132 + ty * 8);
        float4 a1 = *(const float4*)(A + k * 132 + ty * 8 + 4);
        float4 b0 = *(const float4*)(Bs + k * 132 + tx * 4);
        float4 b1 = *(const float4*)(Bs + k * 132 + 64 + tx * 4);
        float av[8] = {a0.x,a0.y,a0.z,a0.w,a1.x,a1.y,a1.z,a1.w};
        float bv[8] = {b0.x,b0.y,b0.z,b0.w,b1.x,b1.y,b1.z,b1.w};
        #pragma unroll
        for (int u = 0; u < 8; u++)
            #pragma unroll
            for (int w = 0; w < 8; w++) acc[u][w] = fmaf(av[u], bv[w], acc[u][w]);
    }
    float* out = g_S0 + (size_t)bh * N_ * N_;
    #pragma unroll
    for (int u = 0; u < 8; u++) {
        int gi = i0 + ty * 8 + u;
        float4 w0 = {acc[u][0], acc[u][1], acc[u][2], acc[u][3]};
        float4 w1 = {acc[u][4], acc[u][5], acc[u][6], acc[u][7]};
        *(float4*)(out + (size_t)gi * N_ + j0 + tx * 4) = w0;
        *(float4*)(out + (size_t)gi * N_ + j0 + 64 + tx * 4) = w1;
    }
}

// ---------------- 5) fused: bias + softmax + alpha + W + Z2 --------------------
#define LPAD 68
#define SM_L   0
#define SM_PQ  17408
#define SM_AS  17920
#define SM_WP  19968
#define SM_WS  24064
#define SM_MSK 24576
#define SM_TOT 24832

__global__ void __launch_bounds__(256, 2)
fused_attn_kernel(const float* __restrict__ link, const int* __restrict__ mask,
                  float* __restrict__ alpha_out) {
    extern __shared__ float sm[];
    float* L   = sm + SM_L;      // [256][68]
    float* pq  = sm + SM_PQ;     // [8][64]
    float* aS  = sm + SM_AS;     // [8][256] bias -> alpha
    float* wp  = sm + SM_WP;     // [8 jc][8 h][64 r]
    float* wsh = sm + SM_WS;     // [8][64]
    int*   msk = (int*)(sm + SM_MSK);

    int bi = blockIdx.x;
    int b = bi >> 8, i = bi & 255;
    int tid = threadIdx.x;

    // A: load link tile (64KB, coalesced float4) into padded smem + pq + mask
    const float4* src = (const float4*)(link + (size_t)bi * (N_ * R_));
    #pragma unroll
    for (int p = 0; p < 16; p++) {
        int l = tid + p * 256;
        float4 v = src[l];
        *(float4*)(L + (l >> 4) * LPAD + ((l & 15) << 2)) = v;
    }
    pq[tid]       = g_Pq[(size_t)bi * 512 + tid];
    pq[tid + 256] = g_Pq[(size_t)bi * 512 + 256 + tid];
    msk[tid] = mask[(size_t)bi * N_ + tid];
    __syncthreads();

    // B: bias[h][j], thread j reads its L row once (conflict-free float4)
    {
        float bias[H_] = {};
        const float* Lr = L + tid * LPAD;
        #pragma unroll
        for (int rc = 0; rc < 16; rc++) {
            float4 lv = *(const float4*)(Lr + rc * 4);
            #pragma unroll
            for (int h = 0; h < H_; h++) {
                float4 pv = *(const float4*)(pq + h * 64 + rc * 4);
                bias[h] = fmaf(lv.x, pv.x, bias[h]);
                bias[h] = fmaf(lv.y, pv.y, bias[h]);
                bias[h] = fmaf(lv.z, pv.z, bias[h]);
                bias[h] = fmaf(lv.w, pv.w, bias[h]);
            }
        }
        #pragma unroll
        for (int h = 0; h < H_; h++) aS[h * N_ + tid] = bias[h];
    }
    __syncthreads();

    // C: softmax, one warp per head (shfl-only reductions)
    {
        int h = tid >> 5, lane = tid & 31;
        const float* s0p = g_S0 + ((size_t)(b * H_ + h) * N_ + i) * N_;
        const float inv = 0.17677669529663687f;   // 1/sqrt(32)
        float v[8];
        float mx = -3.4e38f;
        #pragma unroll
        for (int k2 = 0; k2 < 8; k2++) {
            int j = lane + k2 * 32;
            float lg = (s0p[j] + aS[h * N_ + j]) * inv;
            if (msk[j] == 0) lg = -1e9f;
            v[k2] = lg;
            mx = fmaxf(mx, lg);
        }
        #pragma unroll
        for (int o = 16; o > 0; o >>= 1) mx = fmaxf(mx, __shfl_xor_sync(0xffffffffu, mx, o));
        float s = 0.f;
        #pragma unroll
        for (int k2 = 0; k2 < 8; k2++) { v[k2] = __expf(v[k2] - mx); s += v[k2]; }
        #pragma unroll
        for (int o = 16; o > 0; o >>= 1) s += __shfl_xor_sync(0xffffffffu, s, o);
        float rs = 1.0f / s;
        float* ap = aS + h * N_;
        float* aout = alpha_out + ((size_t)(b * H_ + h) * N_ + i) * N_;
        #pragma unroll
        for (int k2 = 0; k2 < 8; k2++) {
            int j = lane + k2 * 32;
            float a = v[k2] * rs;
            ap[j] = a;
            aout[j] = a;
        }
    }
    __syncthreads();

    // D: W[h][r] partials — warp jc handles 32 j's; L read exactly once
    {
        int jc = tid >> 5, rp = tid & 31;   // r = 2*rp, 2*rp+1
        const float* Lp = L + (jc * 32) * LPAD + rp * 2;
        float2 acc[H_];
        #pragma unroll
        for (int h = 0; h < H_; h++) { acc[h].x = 0.f; acc[h].y = 0.f; }
        #pragma unroll 4
        for (int u = 0; u < 32; u++) {
            int j = jc * 32 + u;
            float2 lv = *(const float2*)(Lp + u * LPAD);
            #pragma unroll
            for (int h = 0; h < H_; h++) {
                float a = aS[h * N_ + j];
                acc[h].x = fmaf(a, lv.x, acc[h].x);
                acc[h].y = fmaf(a, lv.y, acc[h].y);
            }
        }
        #pragma unroll
        for (int h = 0; h < H_; h++)
            *(float2*)(wp + jc * 512 + h * 64 + rp * 2) = acc[h];
    }
    __syncthreads();
    {   // reduce 8 partials -> wsh[8][64]
        #pragma unroll
        for (int p = 0; p < 2; p++) {
            int idx = tid + p * 256;
            float s = 0.f;
            #pragma unroll
            for (int jc = 0; jc < 8; jc++) s += wp[jc * 512 + idx];
            wsh[idx] = s;
        }
    }
    __syncthreads();

    // E: Z2[h][d] = sum_r W[h][r] * EV[r][h*32+d]
    {
        int h = tid >> 5, d = tid & 31;
        float acc = 0.f;
        const float* wr = wsh + h * 64;
        const float* ev = g_EV + h * 32 + d;
        #pragma unroll 8
        for (int r = 0; r < R_; r++) acc = fmaf(wr[r], ev[(size_t)r * D_], acc);
        g_Z2[((size_t)(b * H_ + h) * N_ + i) * DV_ + d] = acc;
    }
}

// ---------------- 6) Z = alpha @ Xv + Z2, head-concat layout --------------------
__global__ void __launch_bounds__(256)
z_kernel(const float* __restrict__ alpha) {
    int bh = blockIdx.y;
    int b = bh >> 3, h = bh & 7;
    int i0 = blockIdx.x * 64;
    __shared__ float A[64][65];
    __shared__ float V[64][33];
    const float* al = alpha + (size_t)bh * N_ * N_;
    const float* Xv = g_Xv + (size_t)bh * N_ * DV_;
    int tid = threadIdx.x;
    int ty = tid >> 5, tx = tid & 31;
    float acc[8] = {};
    for (int j0 = 0; j0 < N_; j0 += 64) {
        for (int l = tid; l < 64 * 64; l += 256) {
            int ii = l >> 6, jj = l & 63;
            A[ii][jj] = al[(size_t)(i0 + ii) * N_ + j0 + jj];
        }
        for (int l = tid; l < 64 * 32; l += 256) {
            int jj = l >> 5, d = l & 31;
            V[jj][d] = Xv[(size_t)(j0 + jj) * DV_ + d];
        }
        __syncthreads();
        #pragma unroll 8
        for (int jj = 0; jj < 64; jj++) {
            float vv = V[jj][tx];
            #pragma unroll
            for (int u = 0; u < 8; u++) acc[u] = fmaf(A[ty * 8 + u][jj], vv, acc[u]);
        }
        __syncthreads();
    }
    #pragma unroll
    for (int u = 0; u < 8; u++) {
        int i = i0 + ty * 8 + u;
        float z = acc[u] + g_Z2[((size_t)bh * N_ + i) * DV_ + tx];
        g_Zc[((size_t)(b * N_ + i)) * D_ + h * DV_ + tx] = z;
    }
}

// ---------------- 7) T = Zc @ Wo -------------------------------------------------
__global__ void __launch_bounds__(256)
out_gemm_kernel(const float* __restrict__ Wo) {
    __shared__ float As[16 * 68];
    __shared__ float Bs[16 * 68];
    int m0 = blockIdx.y * 64, n0 = blockIdx.x * 64;
    int tid = threadIdx.x;
    int tx = tid & 15, ty = tid >> 4;
    float acc[4][4] = {};
    const float4* Z4 = (const float4*)g_Zc;
    const float4* W4 = (const float4*)Wo;
    for (int k0 = 0; k0 < D_; k0 += 16) {
        {
            int m = tid >> 2, kq = tid & 3;
            float4 v = Z4[(size_t)(m0 + m) * 64 + (k0 >> 2) + kq];
            As[(4*kq+0)*68 + m] = v.x; As[(4*kq+1)*68 + m] = v.y;
            As[(4*kq+2)*68 + m] = v.z; As[(4*kq+3)*68 + m] = v.w;
        }
        {
            int k = tid >> 4, nq = tid & 15;
            float4 v = W4[(size_t)(k0 + k) * 64 + (n0 >> 2) + nq];
            *(float4*)(Bs + k * 68 + nq * 4) = v;
        }
        __syncthreads();
        #pragma unroll
        for (int k = 0; k < 16; k++) {
            float4 a = *(const float4*)(As + k * 68 + ty * 4);
            float4 b = *(const float4*)(Bs + k * 68 + tx * 4);
            float av[4] = {a.x, a.y, a.z, a.w};
            float bv[4] = {b.x, b.y, b.z, b.w};
            #pragma unroll
            for (int u = 0; u < 4; u++)
                #pragma unroll
                for (int w = 0; w < 4; w++) acc[u][w] = fmaf(av[u], bv[w], acc[u][w]);
        }
        __syncthreads();
    }
    #pragma unroll
    for (int u = 0; u < 4; u++)
        #pragma unroll
        for (int w = 0; w < 4; w++)
            g_T[(size_t)(m0 + ty * 4 + u) * D_ + n0 + tx * 4 + w] = acc[u][w];
}

// ---------------- 8) residual + LayerNorm ---------------------------------------
__global__ void __launch_bounds__(256)
ln_kernel(const float* __restrict__ qin, const float* __restrict__ gamma,
          const float* __restrict__ beta, float* __restrict__ out) {
    __shared__ float red[16];
    int row = blockIdx.x;
    int e = threadIdx.x;
    float t = g_T[(size_t)row * D_ + e] + qin[(size_t)row * D_ + e];
    float mu = block_reduce_sum(t, red) * (1.0f / 256.0f);
    float dv = t - mu;
    float var = block_reduce_sum(dv * dv, red) * (1.0f / 256.0f);
    out[(size_t)row * D_ + e] = dv * rsqrtf(var + EPS_) * gamma[e] + beta[e];
}

// ---------------- launch ---------------------------------------------------------
extern "C" void kernel_launch(void* const* d_in, const int* in_sizes, int n_in,
                              void* d_out, int out_size) {
    const float* q    = (const float*)d_in[0];
    const int*   mask = (const int*)  d_in[3];
    const float* link = (const float*)d_in[4];
    const float* Wq   = (const float*)d_in[5];
    const float* Wk   = (const float*)d_in[6];
    const float* Wr   = (const float*)d_in[7];
    const float* Wv   = (const float*)d_in[8];
    const float* Wvv  = (const float*)d_in[9];
    const float* relE = (const float*)d_in[10];
    const float* Wo   = (const float*)d_in[11];
    const float* gamma= (const float*)d_in[12];
    const float* beta = (const float*)d_in[13];

    float* out_ptr   = (float*)d_out;
    float* alpha_ptr = (float*)d_out + (size_t)B_ * N_ * D_;

    static const size_t smemC = SM_TOT * sizeof(float);
    cudaFuncSetAttribute(fused_attn_kernel,
                         cudaFuncAttributeMaxDynamicSharedMemorySize, (int)smemC);

    calcE_kernel<<<dim3(R_, 2), 256>>>(relE, Wr, Wvv);
    proj_kernel<<<dim3(D_ / 64, BN_ / 64, 3), 256>>>(q, Wq, Wk, Wv);
    pq_kernel<<<dim3(H_, B_, 4), 256>>>();
    s0_kernel<<<dim3(2, 2, B_ * H_), 256>>>();
    fused_attn_kernel<<<BN_, 256, smemC>>>(link, mask, alpha_ptr);
    z_kernel<<<dim3(N_ / 64, B_ * H_), 256>>>(alpha_ptr);
    out_gemm_kernel<<<dim3(D_ / 64, BN_ / 64), 256>>>(Wo);
    ln_kernel<<<BN_, 256>>>(q, gamma, beta, out_ptr);
}